// round 5
// baseline (speedup 1.0000x reference)
#include <cuda_runtime.h>
#include <math.h>

#define BATCH 2
#define SEQ   2048
#define EMB   1024
#define NH    16
#define HD    64
#define MTOT  (BATCH*SEQ)   // 4096

// ---------------- device scratch (no allocations allowed) ----------------
__device__ float g_Qt[(size_t)BATCH * NH * HD * SEQ];   // [B,H,Dh,S]  transposed
__device__ float g_Kt[(size_t)BATCH * NH * HD * SEQ];   // [B,H,Dh,S]  transposed
__device__ float g_V [(size_t)BATCH * NH * SEQ * HD];   // [B,H,S,Dh]
__device__ float g_ctx[(size_t)MTOT * EMB];             // [B*S, E] head-concat

// =========================================================================
// Kernel 1: fused QKV projection.  Tile 128(M) x 128(N = 2 heads), Kblk=16,
// 256 threads, 8x8 frags, double-buffered smem (1 sync per K-tile).
//   z = 0 (Q, transposed out), 1 (K, transposed out), 2 (V, normal out)
// =========================================================================
__global__ __launch_bounds__(256) void proj_qkv_kernel(
    const float* __restrict__ qin, const float* __restrict__ kin, const float* __restrict__ vin,
    const float* __restrict__ Wq,  const float* __restrict__ Wk,  const float* __restrict__ Wv,
    const float* __restrict__ bq,  const float* __restrict__ bk,  const float* __restrict__ bv)
{
    // As[2][16][132] @ 0,2112 ; Bs[2][16][136] @ 4224,6400 ; Cs[128][65] reuse
    __shared__ float smem[8576];

    const int z  = blockIdx.z;
    const int hp = blockIdx.y;            // head pair
    const int mb = blockIdx.x;
    const int h0 = hp * 2;

    const float* A    = (z == 0) ? qin : (z == 1) ? kin : vin;
    const float* W    = ((z == 0) ? Wq : (z == 1) ? Wk : Wv) + (size_t)h0 * EMB * HD;
    const float* bias = ((z == 0) ? bq : (z == 1) ? bk : bv) + h0 * HD;

    const int tid = threadIdx.x;
    const int tx  = tid & 15;             // n-group: cols tx*8..+7 (of 128)
    const int ty  = tid >> 4;             // m-group: rows ty*8..+7 (of 128)
    const int lc  = tid & 3;              // A loader k-quad
    const int lm  = tid >> 2;             // A loader row (0..63), +64
    const int bkr = tid >> 4;             // B loader k row (0..15)
    const int bn  = tid & 15;             // B loader col8 (0..15)

    const float* Ag = A + (size_t)(mb * 128) * EMB;
    // per-thread B base: head (bn>>3), col (bn&7)*8
    const float* Bg = W + (size_t)(bn >> 3) * EMB * HD + (bn & 7) * 8;

    float acc[8][8];
    #pragma unroll
    for (int i = 0; i < 8; i++)
        #pragma unroll
        for (int j = 0; j < 8; j++) acc[i][j] = 0.f;

    float4 pa0 = *(const float4*)(Ag + (size_t)lm        * EMB + lc * 4);
    float4 pa1 = *(const float4*)(Ag + (size_t)(lm + 64) * EMB + lc * 4);
    float4 pb0 = *(const float4*)(Bg + (size_t)bkr * HD);
    float4 pb1 = *(const float4*)(Bg + (size_t)bkr * HD + 4);

    // stage tile 0 into buffer 0
    {
        float* As_ = smem;
        float* Bs_ = smem + 4224;
        As_[(lc*4+0)*132 + lm] = pa0.x; As_[(lc*4+1)*132 + lm] = pa0.y;
        As_[(lc*4+2)*132 + lm] = pa0.z; As_[(lc*4+3)*132 + lm] = pa0.w;
        As_[(lc*4+0)*132 + lm+64] = pa1.x; As_[(lc*4+1)*132 + lm+64] = pa1.y;
        As_[(lc*4+2)*132 + lm+64] = pa1.z; As_[(lc*4+3)*132 + lm+64] = pa1.w;
        *(float4*)(Bs_ + bkr*136 + bn*8)     = pb0;
        *(float4*)(Bs_ + bkr*136 + bn*8 + 4) = pb1;
    }
    __syncthreads();

    for (int it = 0; it < 64; ++it) {
        const int cur = it & 1;
        if (it < 63) {                    // prefetch next tile into registers
            const int k = (it + 1) * 16;
            pa0 = *(const float4*)(Ag + (size_t)lm        * EMB + k + lc * 4);
            pa1 = *(const float4*)(Ag + (size_t)(lm + 64) * EMB + k + lc * 4);
            pb0 = *(const float4*)(Bg + (size_t)(k + bkr) * HD);
            pb1 = *(const float4*)(Bg + (size_t)(k + bkr) * HD + 4);
        }
        const float* As_ = smem + cur * 2112;
        const float* Bs_ = smem + 4224 + cur * 2176;
        #pragma unroll
        for (int kk = 0; kk < 16; kk++) {
            float4 a0 = *(const float4*)(As_ + kk*132 + ty*8);
            float4 a1 = *(const float4*)(As_ + kk*132 + ty*8 + 4);
            float4 b0 = *(const float4*)(Bs_ + kk*136 + tx*8);
            float4 b1 = *(const float4*)(Bs_ + kk*136 + tx*8 + 4);
            float av[8] = {a0.x,a0.y,a0.z,a0.w,a1.x,a1.y,a1.z,a1.w};
            float bv[8] = {b0.x,b0.y,b0.z,b0.w,b1.x,b1.y,b1.z,b1.w};
            #pragma unroll
            for (int i = 0; i < 8; i++)
                #pragma unroll
                for (int j = 0; j < 8; j++)
                    acc[i][j] = fmaf(av[i], bv[j], acc[i][j]);
        }
        if (it < 63) {
            float* Asn = smem + (1 - cur) * 2112;
            float* Bsn = smem + 4224 + (1 - cur) * 2176;
            Asn[(lc*4+0)*132 + lm] = pa0.x; Asn[(lc*4+1)*132 + lm] = pa0.y;
            Asn[(lc*4+2)*132 + lm] = pa0.z; Asn[(lc*4+3)*132 + lm] = pa0.w;
            Asn[(lc*4+0)*132 + lm+64] = pa1.x; Asn[(lc*4+1)*132 + lm+64] = pa1.y;
            Asn[(lc*4+2)*132 + lm+64] = pa1.z; Asn[(lc*4+3)*132 + lm+64] = pa1.w;
            *(float4*)(Bsn + bkr*136 + bn*8)     = pb0;
            *(float4*)(Bsn + bkr*136 + bn*8 + 4) = pb1;
            __syncthreads();
        }
    }

    // bias (cols tx*8..+7 live inside head hh = tx>>3)
    const int hh = tx >> 3;
    {
        float4 bb0 = *(const float4*)(bias + hh * HD + (tx & 7) * 8);
        float4 bb1 = *(const float4*)(bias + hh * HD + (tx & 7) * 8 + 4);
        float bv[8] = {bb0.x,bb0.y,bb0.z,bb0.w,bb1.x,bb1.y,bb1.z,bb1.w};
        #pragma unroll
        for (int i = 0; i < 8; i++)
            #pragma unroll
            for (int j = 0; j < 8; j++) acc[i][j] += bv[j];
    }

    const int gm0 = mb * 128;
    const int b   = gm0 >> 11;
    const int s0  = gm0 & 2047;

    if (z == 2) {
        // V: [B,H,S,Dh]
        float* Vout = g_V + ((size_t)(b * NH + h0 + hh) * SEQ + s0) * HD + (tx & 7) * 8;
        #pragma unroll
        for (int i = 0; i < 8; i++) {
            float4 v0 = make_float4(acc[i][0], acc[i][1], acc[i][2], acc[i][3]);
            float4 v1 = make_float4(acc[i][4], acc[i][5], acc[i][6], acc[i][7]);
            *(float4*)(Vout + (size_t)(ty*8 + i) * HD)     = v0;
            *(float4*)(Vout + (size_t)(ty*8 + i) * HD + 4) = v1;
        }
    } else {
        // Q/K transposed: two passes (one per head) through Cs[128][65]
        float* Cs = smem;
        #pragma unroll
        for (int hq = 0; hq < 2; hq++) {
            __syncthreads();
            if (hh == hq) {
                #pragma unroll
                for (int i = 0; i < 8; i++)
                    #pragma unroll
                    for (int j = 0; j < 8; j++)
                        Cs[(ty*8 + i) * 65 + (tx & 7) * 8 + j] = acc[i][j];
            }
            __syncthreads();
            float* outT = ((z == 0) ? g_Qt : g_Kt)
                        + (size_t)(b * NH + h0 + hq) * HD * SEQ + s0;
            const int dlo = tid >> 5;          // 0..7
            const int s4  = (tid & 31) * 4;    // 0..124
            #pragma unroll
            for (int p = 0; p < 8; p++) {
                int dd = dlo + p * 8;
                float4 v4;
                v4.x = Cs[(s4 + 0) * 65 + dd];
                v4.y = Cs[(s4 + 1) * 65 + dd];
                v4.z = Cs[(s4 + 2) * 65 + dd];
                v4.w = Cs[(s4 + 3) * 65 + dd];
                *(float4*)(outT + (size_t)dd * SEQ + s4) = v4;
            }
        }
    }
}

// =========================================================================
// Kernel 2: flash attention fp32.  Q tile 128, KV tile 64, 128 threads,
// 8x8 frags in both GEMMs.  P staged TRANSPOSED [kv][q] so PV reads are
// float4 along q (conflict-free).  Per-thread softmax state (same q rows
// in S and PV mappings).  Dynamic smem 100352B -> 2 blocks/SM.
// =========================================================================
__global__ __launch_bounds__(128) void flash_kernel()
{
    extern __shared__ float sm[];
    float* Qs = sm;              // [64][128]  d-major, pre-scaled
    float* Ks = sm + 8192;       // [64][64]   d-major
    float* Vs = sm + 12288;      // [64][68]   kv-major
    float* Pt = sm + 16640;      // [64][132]  P transposed [kv][q]

    const int qb = blockIdx.x, h = blockIdx.y, b = blockIdx.z;
    const size_t bh = (size_t)(b * NH + h);
    const float* Qg = g_Qt + bh * HD * SEQ + qb * 128;
    const float* Kg = g_Kt + bh * HD * SEQ;
    const float* Vg = g_V  + bh * SEQ * HD;

    const int tid = threadIdx.x;
    const int tx = tid & 7;      // kv-group (S) / d-group (PV): cols tx*8..+7
    const int ty = tid >> 3;     // q-group: rows ty*8..+7

    // load Q tile once, fold in 1/sqrt(64)
    #pragma unroll
    for (int p = 0; p < 16; p++) {
        int i = tid + 128 * p;
        int row = i >> 5, col4 = (i & 31) * 4;
        float4 g = *(const float4*)(Qg + (size_t)row * SEQ + col4);
        g.x *= 0.125f; g.y *= 0.125f; g.z *= 0.125f; g.w *= 0.125f;
        *(float4*)(Qs + row * 128 + col4) = g;
    }

    float o[8][8];
    #pragma unroll
    for (int j = 0; j < 8; j++)
        #pragma unroll
        for (int d = 0; d < 8; d++) o[j][d] = 0.f;
    float m_r[8], l_r[8];
    #pragma unroll
    for (int j = 0; j < 8; j++) { m_r[j] = -1e30f; l_r[j] = 0.f; }

    for (int t0 = 0; t0 < SEQ; t0 += 64) {
        __syncthreads();   // Qs ready (iter 0) / prior PV done with Ks,Vs,Pt
        #pragma unroll
        for (int p = 0; p < 8; p++) {
            int i = tid + 128 * p;
            int row = i >> 4, col4 = (i & 15) * 4;
            *(float4*)(Ks + row * 64 + col4) =
                *(const float4*)(Kg + (size_t)row * SEQ + t0 + col4);
            *(float4*)(Vs + row * 68 + col4) =
                *(const float4*)(Vg + (size_t)(t0 + row) * HD + col4);
        }
        __syncthreads();

        // S = Q K^T : 8x8 frag, inner over d
        float s[8][8];
        #pragma unroll
        for (int j = 0; j < 8; j++)
            #pragma unroll
            for (int i = 0; i < 8; i++) s[j][i] = 0.f;
        #pragma unroll 8
        for (int d = 0; d < 64; d++) {
            float4 a0 = *(const float4*)(Qs + d * 128 + ty * 8);
            float4 a1 = *(const float4*)(Qs + d * 128 + ty * 8 + 4);
            float4 b0 = *(const float4*)(Ks + d * 64 + tx * 8);
            float4 b1 = *(const float4*)(Ks + d * 64 + tx * 8 + 4);
            float av[8] = {a0.x,a0.y,a0.z,a0.w,a1.x,a1.y,a1.z,a1.w};
            float kv[8] = {b0.x,b0.y,b0.z,b0.w,b1.x,b1.y,b1.z,b1.w};
            #pragma unroll
            for (int j = 0; j < 8; j++)
                #pragma unroll
                for (int i = 0; i < 8; i++)
                    s[j][i] = fmaf(av[j], kv[i], s[j][i]);
        }

        // online softmax per q-row (reduce across the 8 tx lanes)
        #pragma unroll
        for (int j = 0; j < 8; j++) {
            float mx = fmaxf(fmaxf(fmaxf(s[j][0], s[j][1]), fmaxf(s[j][2], s[j][3])),
                             fmaxf(fmaxf(s[j][4], s[j][5]), fmaxf(s[j][6], s[j][7])));
            mx = fmaxf(mx, __shfl_xor_sync(0xffffffffu, mx, 1));
            mx = fmaxf(mx, __shfl_xor_sync(0xffffffffu, mx, 2));
            mx = fmaxf(mx, __shfl_xor_sync(0xffffffffu, mx, 4));
            float mn = fmaxf(m_r[j], mx);
            float sc = __expf(m_r[j] - mn);
            m_r[j] = mn;
            float rs = 0.f;
            #pragma unroll
            for (int i = 0; i < 8; i++) {
                s[j][i] = __expf(s[j][i] - mn);
                rs += s[j][i];
            }
            rs += __shfl_xor_sync(0xffffffffu, rs, 1);
            rs += __shfl_xor_sync(0xffffffffu, rs, 2);
            rs += __shfl_xor_sync(0xffffffffu, rs, 4);
            l_r[j] = l_r[j] * sc + rs;
            #pragma unroll
            for (int d = 0; d < 8; d++) o[j][d] *= sc;
        }

        // store P transposed [kv][q]: float4 over q
        #pragma unroll
        for (int i = 0; i < 8; i++) {
            float4 f0 = make_float4(s[0][i], s[1][i], s[2][i], s[3][i]);
            float4 f1 = make_float4(s[4][i], s[5][i], s[6][i], s[7][i]);
            *(float4*)(Pt + (tx*8 + i) * 132 + ty*8)     = f0;
            *(float4*)(Pt + (tx*8 + i) * 132 + ty*8 + 4) = f1;
        }
        __syncthreads();

        // O += P V : 8x8 frag, inner over kv in chunks of 4
        #pragma unroll 4
        for (int kk = 0; kk < 64; kk += 4) {
            float4 p0[4], p1[4], v0[4], v1[4];
            #pragma unroll
            for (int r = 0; r < 4; r++) {
                p0[r] = *(const float4*)(Pt + (kk + r) * 132 + ty * 8);
                p1[r] = *(const float4*)(Pt + (kk + r) * 132 + ty * 8 + 4);
                v0[r] = *(const float4*)(Vs + (kk + r) * 68 + tx * 8);
                v1[r] = *(const float4*)(Vs + (kk + r) * 68 + tx * 8 + 4);
            }
            #pragma unroll
            for (int r = 0; r < 4; r++) {
                float pv[8] = {p0[r].x,p0[r].y,p0[r].z,p0[r].w,
                               p1[r].x,p1[r].y,p1[r].z,p1[r].w};
                float vv[8] = {v0[r].x,v0[r].y,v0[r].z,v0[r].w,
                               v1[r].x,v1[r].y,v1[r].z,v1[r].w};
                #pragma unroll
                for (int j = 0; j < 8; j++)
                    #pragma unroll
                    for (int d = 0; d < 8; d++)
                        o[j][d] = fmaf(pv[j], vv[d], o[j][d]);
            }
        }
    }

    // normalize + write ctx [B*S, E]
    float* Cg = g_ctx + ((size_t)b * SEQ + qb * 128) * EMB + h * HD + tx * 8;
    #pragma unroll
    for (int j = 0; j < 8; j++) {
        float inv = 1.0f / l_r[j];
        float4 r0 = make_float4(o[j][0]*inv, o[j][1]*inv, o[j][2]*inv, o[j][3]*inv);
        float4 r1 = make_float4(o[j][4]*inv, o[j][5]*inv, o[j][6]*inv, o[j][7]*inv);
        *(float4*)(Cg + (size_t)(ty*8 + j) * EMB)     = r0;
        *(float4*)(Cg + (size_t)(ty*8 + j) * EMB + 4) = r1;
    }
}

// =========================================================================
// Kernel 3: output projection.  out[4096 x 1024] = ctx * Wo + bo
// Tile 128x128, 256 threads, 8x8 frags, double-buffered smem.
// =========================================================================
__global__ __launch_bounds__(256) void outproj_kernel(
    const float* __restrict__ Wo, const float* __restrict__ bo, float* __restrict__ out)
{
    __shared__ float smem[8576];   // As[2][16][132] + Bs[2][16][136]

    const int nb = blockIdx.y;
    const int mb = blockIdx.x;
    const int tid = threadIdx.x;
    const int tx  = tid & 15;
    const int ty  = tid >> 4;
    const int lc  = tid & 3;
    const int lm  = tid >> 2;
    const int bkr = tid >> 4;
    const int bn  = tid & 15;

    const float* Ag = g_ctx + (size_t)(mb * 128) * EMB;
    const float* Bg = Wo + nb * 128 + bn * 8;

    float acc[8][8];
    #pragma unroll
    for (int i = 0; i < 8; i++)
        #pragma unroll
        for (int j = 0; j < 8; j++) acc[i][j] = 0.f;

    float4 pa0 = *(const float4*)(Ag + (size_t)lm        * EMB + lc * 4);
    float4 pa1 = *(const float4*)(Ag + (size_t)(lm + 64) * EMB + lc * 4);
    float4 pb0 = *(const float4*)(Bg + (size_t)bkr * EMB);
    float4 pb1 = *(const float4*)(Bg + (size_t)bkr * EMB + 4);

    {
        float* As_ = smem;
        float* Bs_ = smem + 4224;
        As_[(lc*4+0)*132 + lm] = pa0.x; As_[(lc*4+1)*132 + lm] = pa0.y;
        As_[(lc*4+2)*132 + lm] = pa0.z; As_[(lc*4+3)*132 + lm] = pa0.w;
        As_[(lc*4+0)*132 + lm+64] = pa1.x; As_[(lc*4+1)*132 + lm+64] = pa1.y;
        As_[(lc*4+2)*132 + lm+64] = pa1.z; As_[(lc*4+3)*132 + lm+64] = pa1.w;
        *(float4*)(Bs_ + bkr*136 + bn*8)     = pb0;
        *(float4*)(Bs_ + bkr*136 + bn*8 + 4) = pb1;
    }
    __syncthreads();

    for (int it = 0; it < 64; ++it) {
        const int cur = it & 1;
        if (it < 63) {
            const int k = (it + 1) * 16;
            pa0 = *(const float4*)(Ag + (size_t)lm        * EMB + k + lc * 4);
            pa1 = *(const float4*)(Ag + (size_t)(lm + 64) * EMB + k + lc * 4);
            pb0 = *(const float4*)(Bg + (size_t)(k + bkr) * EMB);
            pb1 = *(const float4*)(Bg + (size_t)(k + bkr) * EMB + 4);
        }
        const float* As_ = smem + cur * 2112;
        const float* Bs_ = smem + 4224 + cur * 2176;
        #pragma unroll
        for (int kk = 0; kk < 16; kk++) {
            float4 a0 = *(const float4*)(As_ + kk*132 + ty*8);
            float4 a1 = *(const float4*)(As_ + kk*132 + ty*8 + 4);
            float4 b0 = *(const float4*)(Bs_ + kk*136 + tx*8);
            float4 b1 = *(const float4*)(Bs_ + kk*136 + tx*8 + 4);
            float av[8] = {a0.x,a0.y,a0.z,a0.w,a1.x,a1.y,a1.z,a1.w};
            float bv[8] = {b0.x,b0.y,b0.z,b0.w,b1.x,b1.y,b1.z,b1.w};
            #pragma unroll
            for (int i = 0; i < 8; i++)
                #pragma unroll
                for (int j = 0; j < 8; j++)
                    acc[i][j] = fmaf(av[i], bv[j], acc[i][j]);
        }
        if (it < 63) {
            float* Asn = smem + (1 - cur) * 2112;
            float* Bsn = smem + 4224 + (1 - cur) * 2176;
            Asn[(lc*4+0)*132 + lm] = pa0.x; Asn[(lc*4+1)*132 + lm] = pa0.y;
            Asn[(lc*4+2)*132 + lm] = pa0.z; Asn[(lc*4+3)*132 + lm] = pa0.w;
            Asn[(lc*4+0)*132 + lm+64] = pa1.x; Asn[(lc*4+1)*132 + lm+64] = pa1.y;
            Asn[(lc*4+2)*132 + lm+64] = pa1.z; Asn[(lc*4+3)*132 + lm+64] = pa1.w;
            *(float4*)(Bsn + bkr*136 + bn*8)     = pb0;
            *(float4*)(Bsn + bkr*136 + bn*8 + 4) = pb1;
            __syncthreads();
        }
    }

    float4 bb0 = *(const float4*)(bo + nb * 128 + tx * 8);
    float4 bb1 = *(const float4*)(bo + nb * 128 + tx * 8 + 4);
    float bvv[8] = {bb0.x,bb0.y,bb0.z,bb0.w,bb1.x,bb1.y,bb1.z,bb1.w};
    float* Cg = out + (size_t)(mb * 128) * EMB + nb * 128 + tx * 8;
    #pragma unroll
    for (int i = 0; i < 8; i++) {
        float4 v0 = make_float4(acc[i][0]+bvv[0], acc[i][1]+bvv[1],
                                acc[i][2]+bvv[2], acc[i][3]+bvv[3]);
        float4 v1 = make_float4(acc[i][4]+bvv[4], acc[i][5]+bvv[5],
                                acc[i][6]+bvv[6], acc[i][7]+bvv[7]);
        *(float4*)(Cg + (size_t)(ty*8 + i) * EMB)     = v0;
        *(float4*)(Cg + (size_t)(ty*8 + i) * EMB + 4) = v1;
    }
}

// =========================================================================
extern "C" void kernel_launch(void* const* d_in, const int* in_sizes, int n_in,
                              void* d_out, int out_size)
{
    const float* q  = (const float*)d_in[0];
    const float* k  = (const float*)d_in[1];
    const float* v  = (const float*)d_in[2];
    const float* Wq = (const float*)d_in[3];
    const float* Wk = (const float*)d_in[4];
    const float* Wv = (const float*)d_in[5];
    const float* bq = (const float*)d_in[6];
    const float* bk = (const float*)d_in[7];
    const float* bv = (const float*)d_in[8];
    const float* Wo = (const float*)d_in[9];
    const float* bo = (const float*)d_in[10];
    float* out = (float*)d_out;

    (void)in_sizes; (void)n_in; (void)out_size;

    // flash needs 100352B dynamic smem (opt-in; host-side attr, capture-safe)
    cudaFuncSetAttribute(flash_kernel,
                         cudaFuncAttributeMaxDynamicSharedMemorySize, 100352);

    // 1) QKV projections (2 heads per block; Q,K transposed [B,H,Dh,S])
    proj_qkv_kernel<<<dim3(32, 8, 3), 256>>>(q, k, v, Wq, Wk, Wv, bq, bk, bv);
    // 2) flash attention -> g_ctx
    flash_kernel<<<dim3(16, 16, 2), 128, 100352>>>();
    // 3) output projection + bias -> d_out
    outproj_kernel<<<dim3(32, 8), 256>>>(Wo, bo, out);
}

// round 8
// speedup vs baseline: 1.5202x; 1.5202x over previous
#include <cuda_runtime.h>
#include <cuda_bf16.h>
#include <cstdint>
#include <math.h>

#define BATCH 2
#define SEQ   2048
#define EMB   1024
#define NH    16
#define HD    64
#define MTOT  (BATCH*SEQ)   // 4096

typedef __nv_bfloat16 BF;

// ---------------- device scratch (no allocations allowed) ----------------
__device__ float g_Qt[(size_t)BATCH * NH * HD * SEQ];   // [B,H,Dh,S]  transposed
__device__ float g_Kt[(size_t)BATCH * NH * HD * SEQ];   // [B,H,Dh,S]  transposed
__device__ float g_V [(size_t)BATCH * NH * SEQ * HD];   // [B,H,S,Dh]
__device__ float g_ctx[(size_t)MTOT * EMB];             // [B*S, E] head-concat

// ---------------- mma.sync helpers ----------------
__device__ __forceinline__ unsigned int smem_u32(const void* p) {
    return (unsigned int)__cvta_generic_to_shared(p);
}

__device__ __forceinline__ void ldsm_x4(unsigned int& r0, unsigned int& r1,
                                        unsigned int& r2, unsigned int& r3,
                                        unsigned int addr) {
    asm volatile("ldmatrix.sync.aligned.m8n8.x4.shared.b16 {%0,%1,%2,%3}, [%4];"
                 : "=r"(r0), "=r"(r1), "=r"(r2), "=r"(r3) : "r"(addr));
}
__device__ __forceinline__ void ldsm_x4t(unsigned int& r0, unsigned int& r1,
                                         unsigned int& r2, unsigned int& r3,
                                         unsigned int addr) {
    asm volatile("ldmatrix.sync.aligned.m8n8.x4.trans.shared.b16 {%0,%1,%2,%3}, [%4];"
                 : "=r"(r0), "=r"(r1), "=r"(r2), "=r"(r3) : "r"(addr));
}
__device__ __forceinline__ void mma16816(float* c, const unsigned int* a, const unsigned int* b) {
    asm volatile(
        "mma.sync.aligned.m16n8k16.row.col.f32.bf16.bf16.f32 "
        "{%0,%1,%2,%3}, {%4,%5,%6,%7}, {%8,%9}, {%0,%1,%2,%3};"
        : "+f"(c[0]), "+f"(c[1]), "+f"(c[2]), "+f"(c[3])
        : "r"(a[0]), "r"(a[1]), "r"(a[2]), "r"(a[3]), "r"(b[0]), "r"(b[1]));
}

// split fp32 -> bf16 hi + bf16 lo (3-term Markidis), store 4 elems (8B each)
union U4 { BF b[4]; uint2 u; };
__device__ __forceinline__ void split_store4(BF* hi, int lo_off, float4 f) {
    U4 H, L;
    H.b[0] = __float2bfloat16_rn(f.x);
    H.b[1] = __float2bfloat16_rn(f.y);
    H.b[2] = __float2bfloat16_rn(f.z);
    H.b[3] = __float2bfloat16_rn(f.w);
    L.b[0] = __float2bfloat16_rn(f.x - __bfloat162float(H.b[0]));
    L.b[1] = __float2bfloat16_rn(f.y - __bfloat162float(H.b[1]));
    L.b[2] = __float2bfloat16_rn(f.z - __bfloat162float(H.b[2]));
    L.b[3] = __float2bfloat16_rn(f.w - __bfloat162float(H.b[3]));
    *(uint2*)hi = H.u;
    *(uint2*)(hi + lo_off) = L.u;
}

// smem tile geometry (shared by both mma GEMMs)
//   Ah [128][40] bf16 @ 0       (10240 B), Al = Ah + 5120 elems
//   Bh [32 ][72] bf16 @ 20480 B (4608 B),  Bl = Bh + 2304 elems
//   Cs [128][65] f32 reuse (33280 B)
#define A_PITCH 40
#define B_PITCH 72
#define A_LO    5120
#define B_LO    2304

// one k16 MMA step: 8 ldmatrix + 24 mma (hi*hi + hi*lo + lo*hi)
__device__ __forceinline__ void mma_step(const BF* Ah, const BF* Bh,
                                         int wm, int wn, int lane, int ks,
                                         float acc[2][4][4]) {
    unsigned int aH[2][4], aL[2][4], bH[4][2], bL[4][2];
    #pragma unroll
    for (int mt = 0; mt < 2; mt++) {
        const BF* p = Ah + (wm + mt * 16 + (lane & 15)) * A_PITCH + ks + (lane >> 4) * 8;
        ldsm_x4(aH[mt][0], aH[mt][1], aH[mt][2], aH[mt][3], smem_u32(p));
        ldsm_x4(aL[mt][0], aL[mt][1], aL[mt][2], aL[mt][3], smem_u32(p + A_LO));
    }
    #pragma unroll
    for (int g = 0; g < 2; g++) {
        int row = ks + ((lane >> 3) & 1) * 8 + (lane & 7);
        int col = wn + g * 16 + (lane >> 4) * 8;
        const BF* p = Bh + row * B_PITCH + col;
        unsigned int t0, t1, t2, t3;
        ldsm_x4t(t0, t1, t2, t3, smem_u32(p));
        bH[2*g][0] = t0; bH[2*g][1] = t1; bH[2*g+1][0] = t2; bH[2*g+1][1] = t3;
        ldsm_x4t(t0, t1, t2, t3, smem_u32(p + B_LO));
        bL[2*g][0] = t0; bL[2*g][1] = t1; bL[2*g+1][0] = t2; bL[2*g+1][1] = t3;
    }
    #pragma unroll
    for (int mt = 0; mt < 2; mt++)
        #pragma unroll
        for (int nt = 0; nt < 4; nt++) {
            mma16816(acc[mt][nt], aH[mt], bH[nt]);
            mma16816(acc[mt][nt], aH[mt], bL[nt]);
            mma16816(acc[mt][nt], aL[mt], bH[nt]);
        }
}

// =========================================================================
// Kernel 1: QKV projection via bf16-split mma.sync.
//   per block: 128 rows x 1 head (64 cols).  z = 0(Q^T) / 1(K^T) / 2(V)
// =========================================================================
__global__ __launch_bounds__(256) void proj_qkv_kernel(
    const float* __restrict__ qin, const float* __restrict__ kin, const float* __restrict__ vin,
    const float* __restrict__ Wq,  const float* __restrict__ Wk,  const float* __restrict__ Wv,
    const float* __restrict__ bq,  const float* __restrict__ bk,  const float* __restrict__ bv)
{
    __shared__ __align__(16) float smf[8320];     // 33280 B
    BF* Ah = (BF*)smf;
    BF* Bh = (BF*)(smf + 5120);                   // byte offset 20480
    float* Cs = smf;                              // [128][65] reuse

    const int z  = blockIdx.z;
    const int h  = blockIdx.y;
    const int mb = blockIdx.x;

    const float* A    = (z == 0) ? qin : (z == 1) ? kin : vin;
    const float* Wg   = ((z == 0) ? Wq : (z == 1) ? Wk : Wv) + (size_t)h * EMB * HD;
    const float* bias = ((z == 0) ? bq : (z == 1) ? bk : bv) + h * HD;

    const int tid  = threadIdx.x;
    const int lane = tid & 31;
    const int wid  = tid >> 5;
    const int wm   = (wid >> 1) * 32;
    const int wn   = (wid & 1) * 32;

    const float* Ag = A + (size_t)(mb * 128) * EMB;

    float acc[2][4][4];
    #pragma unroll
    for (int a = 0; a < 2; a++)
        #pragma unroll
        for (int b2 = 0; b2 < 4; b2++)
            #pragma unroll
            for (int c = 0; c < 4; c++) acc[a][b2][c] = 0.f;

    // loader coords
    int arow[4], acol[4], brow[2], bcol[2];
    #pragma unroll
    for (int p = 0; p < 4; p++) { int i = tid + 256 * p; arow[p] = i >> 3; acol[p] = (i & 7) * 4; }
    #pragma unroll
    for (int p = 0; p < 2; p++) { int i = tid + 256 * p; brow[p] = i >> 4; bcol[p] = (i & 15) * 4; }

    float4 fa[4], fb[2];
    #pragma unroll
    for (int p = 0; p < 4; p++) fa[p] = *(const float4*)(Ag + (size_t)arow[p] * EMB + acol[p]);
    #pragma unroll
    for (int p = 0; p < 2; p++) fb[p] = *(const float4*)(Wg + (size_t)brow[p] * HD + bcol[p]);

    for (int it = 0; it < 32; ++it) {
        __syncthreads();
        #pragma unroll
        for (int p = 0; p < 4; p++)
            split_store4(Ah + arow[p] * A_PITCH + acol[p], A_LO, fa[p]);
        #pragma unroll
        for (int p = 0; p < 2; p++)
            split_store4(Bh + brow[p] * B_PITCH + bcol[p], B_LO, fb[p]);
        __syncthreads();

        if (it < 31) {
            const int kn = (it + 1) * 32;
            #pragma unroll
            for (int p = 0; p < 4; p++)
                fa[p] = *(const float4*)(Ag + (size_t)arow[p] * EMB + kn + acol[p]);
            #pragma unroll
            for (int p = 0; p < 2; p++)
                fb[p] = *(const float4*)(Wg + (size_t)(kn + brow[p]) * HD + bcol[p]);
        }
        mma_step(Ah, Bh, wm, wn, lane, 0,  acc);
        mma_step(Ah, Bh, wm, wn, lane, 16, acc);
    }

    // stage C into smem (overwrites A/B tiles)
    __syncthreads();
    {
        const int r0 = wm + (lane >> 2);
        const int c0 = wn + 2 * (lane & 3);
        #pragma unroll
        for (int mt = 0; mt < 2; mt++)
            #pragma unroll
            for (int nt = 0; nt < 4; nt++) {
                int r = r0 + mt * 16, c = c0 + nt * 8;
                Cs[r * 65 + c]           = acc[mt][nt][0];
                Cs[r * 65 + c + 1]       = acc[mt][nt][1];
                Cs[(r + 8) * 65 + c]     = acc[mt][nt][2];
                Cs[(r + 8) * 65 + c + 1] = acc[mt][nt][3];
            }
    }
    __syncthreads();

    const int gm0 = mb * 128;
    const int b   = gm0 >> 11;
    const int s0  = gm0 & 2047;

    if (z == 2) {
        float* Vout = g_V + ((size_t)(b * NH + h) * SEQ + s0) * HD;
        for (int i = tid; i < 8192; i += 256) {
            int r = i >> 6, c = i & 63;
            Vout[(size_t)r * HD + c] = Cs[r * 65 + c] + bias[c];
        }
    } else {
        float* outT = ((z == 0) ? g_Qt : g_Kt) + (size_t)(b * NH + h) * HD * SEQ + s0;
        const int dlo = tid >> 5;          // 0..7
        const int s4  = (tid & 31) * 4;    // 0..124
        #pragma unroll
        for (int p = 0; p < 8; p++) {
            int dd = dlo + p * 8;
            float bsv = bias[dd];
            float4 v4;
            v4.x = Cs[(s4 + 0) * 65 + dd] + bsv;
            v4.y = Cs[(s4 + 1) * 65 + dd] + bsv;
            v4.z = Cs[(s4 + 2) * 65 + dd] + bsv;
            v4.w = Cs[(s4 + 3) * 65 + dd] + bsv;
            *(float4*)(outT + (size_t)dd * SEQ + s4) = v4;
        }
    }
}

// =========================================================================
// Kernel 2: flash attention fp32 (R3 version, known-good).
// =========================================================================
__global__ __launch_bounds__(256) void flash_kernel()
{
    extern __shared__ float sm[];
    float* Qs  = sm;            // [64][64]
    float* KPs = sm + 4096;     // [64][64]  K tile, then P tile
    float* Vs  = sm + 8192;     // [64][64]

    const int qb = blockIdx.x, h = blockIdx.y, b = blockIdx.z;
    const size_t bh = (size_t)(b * NH + h);
    const float* Qg = g_Qt + bh * HD * SEQ + qb * 64;
    const float* Kg = g_Kt + bh * HD * SEQ;
    const float* Vg = g_V  + bh * SEQ * HD;

    const int tid = threadIdx.x;
    const int tx = tid & 15, ty = tid >> 4;
    const int lr = tid >> 4, lc4 = (tid & 15) * 4;

    #pragma unroll
    for (int p = 0; p < 4; p++) {
        int d = lr + p * 16;
        float4 g = *(const float4*)(Qg + (size_t)d * SEQ + lc4);
        g.x *= 0.125f; g.y *= 0.125f; g.z *= 0.125f; g.w *= 0.125f;
        *(float4*)(Qs + d * 64 + lc4) = g;
    }

    float o[4][4];
    #pragma unroll
    for (int j = 0; j < 4; j++)
        #pragma unroll
        for (int i = 0; i < 4; i++) o[j][i] = 0.f;
    float m_r[4] = {-1e30f, -1e30f, -1e30f, -1e30f};
    float l_r[4] = {0.f, 0.f, 0.f, 0.f};

    for (int t0 = 0; t0 < SEQ; t0 += 64) {
        __syncthreads();
        #pragma unroll
        for (int p = 0; p < 4; p++) {
            int r = lr + p * 16;
            *(float4*)(KPs + r * 64 + lc4) = *(const float4*)(Kg + (size_t)r * SEQ + t0 + lc4);
            *(float4*)(Vs  + r * 64 + lc4) = *(const float4*)(Vg + (size_t)(t0 + r) * HD + lc4);
        }
        __syncthreads();

        float s[4][4];
        #pragma unroll
        for (int j = 0; j < 4; j++)
            #pragma unroll
            for (int i = 0; i < 4; i++) s[j][i] = 0.f;
        #pragma unroll 8
        for (int d = 0; d < 64; d++) {
            float4 a  = *(const float4*)(Qs  + d * 64 + ty * 4);
            float4 kv = *(const float4*)(KPs + d * 64 + tx * 4);
            float ar[4] = {a.x, a.y, a.z, a.w};
            float kr[4] = {kv.x, kv.y, kv.z, kv.w};
            #pragma unroll
            for (int j = 0; j < 4; j++)
                #pragma unroll
                for (int i = 0; i < 4; i++)
                    s[j][i] = fmaf(ar[j], kr[i], s[j][i]);
        }

        #pragma unroll
        for (int j = 0; j < 4; j++) {
            float mx = fmaxf(fmaxf(s[j][0], s[j][1]), fmaxf(s[j][2], s[j][3]));
            mx = fmaxf(mx, __shfl_xor_sync(0xffffffffu, mx, 1));
            mx = fmaxf(mx, __shfl_xor_sync(0xffffffffu, mx, 2));
            mx = fmaxf(mx, __shfl_xor_sync(0xffffffffu, mx, 4));
            mx = fmaxf(mx, __shfl_xor_sync(0xffffffffu, mx, 8));
            float mn = fmaxf(m_r[j], mx);
            float sc = __expf(m_r[j] - mn);
            m_r[j] = mn;
            float rs = 0.f;
            #pragma unroll
            for (int i = 0; i < 4; i++) {
                s[j][i] = __expf(s[j][i] - mn);
                rs += s[j][i];
            }
            rs += __shfl_xor_sync(0xffffffffu, rs, 1);
            rs += __shfl_xor_sync(0xffffffffu, rs, 2);
            rs += __shfl_xor_sync(0xffffffffu, rs, 4);
            rs += __shfl_xor_sync(0xffffffffu, rs, 8);
            l_r[j] = l_r[j] * sc + rs;
            #pragma unroll
            for (int i = 0; i < 4; i++) o[j][i] *= sc;
        }

        __syncthreads();
        #pragma unroll
        for (int j = 0; j < 4; j++) {
            float4 p4 = make_float4(s[j][0], s[j][1], s[j][2], s[j][3]);
            *(float4*)(KPs + (ty * 4 + j) * 64 + tx * 4) = p4;
        }
        __syncthreads();

        #pragma unroll 4
        for (int kk = 0; kk < 64; kk += 4) {
            float4 pa[4], vb[4];
            #pragma unroll
            for (int j = 0; j < 4; j++)
                pa[j] = *(const float4*)(KPs + (ty * 4 + j) * 64 + kk);
            #pragma unroll
            for (int i2 = 0; i2 < 4; i2++)
                vb[i2] = *(const float4*)(Vs + (kk + i2) * 64 + tx * 4);
            const float* vbp = (const float*)vb;
            #pragma unroll
            for (int j = 0; j < 4; j++) {
                float par[4] = {pa[j].x, pa[j].y, pa[j].z, pa[j].w};
                #pragma unroll
                for (int c = 0; c < 4; c++) {
                    float t = o[j][c];
                    t = fmaf(par[0], vbp[0 * 4 + c], t);
                    t = fmaf(par[1], vbp[1 * 4 + c], t);
                    t = fmaf(par[2], vbp[2 * 4 + c], t);
                    t = fmaf(par[3], vbp[3 * 4 + c], t);
                    o[j][c] = t;
                }
            }
        }
    }

    float* Cg = g_ctx + ((size_t)b * SEQ + qb * 64) * EMB + h * HD;
    #pragma unroll
    for (int j = 0; j < 4; j++) {
        float inv = 1.0f / l_r[j];
        float4 r4 = make_float4(o[j][0] * inv, o[j][1] * inv, o[j][2] * inv, o[j][3] * inv);
        *(float4*)(Cg + (size_t)(ty * 4 + j) * EMB + tx * 4) = r4;
    }
}

// =========================================================================
// Kernel 3: output projection via bf16-split mma.sync.
//   per block: 128 rows x 64 cols of out = ctx * Wo + bo
// =========================================================================
__global__ __launch_bounds__(256) void outproj_kernel(
    const float* __restrict__ Wo, const float* __restrict__ bo, float* __restrict__ out)
{
    __shared__ __align__(16) float smf[8320];
    BF* Ah = (BF*)smf;
    BF* Bh = (BF*)(smf + 5120);
    float* Cs = smf;

    const int nb = blockIdx.y;
    const int mb = blockIdx.x;

    const int tid  = threadIdx.x;
    const int lane = tid & 31;
    const int wid  = tid >> 5;
    const int wm   = (wid >> 1) * 32;
    const int wn   = (wid & 1) * 32;

    const float* Ag = g_ctx + (size_t)(mb * 128) * EMB;
    const float* Wg = Wo + nb * 64;

    float acc[2][4][4];
    #pragma unroll
    for (int a = 0; a < 2; a++)
        #pragma unroll
        for (int b2 = 0; b2 < 4; b2++)
            #pragma unroll
            for (int c = 0; c < 4; c++) acc[a][b2][c] = 0.f;

    int arow[4], acol[4], brow[2], bcol[2];
    #pragma unroll
    for (int p = 0; p < 4; p++) { int i = tid + 256 * p; arow[p] = i >> 3; acol[p] = (i & 7) * 4; }
    #pragma unroll
    for (int p = 0; p < 2; p++) { int i = tid + 256 * p; brow[p] = i >> 4; bcol[p] = (i & 15) * 4; }

    float4 fa[4], fb[2];
    #pragma unroll
    for (int p = 0; p < 4; p++) fa[p] = *(const float4*)(Ag + (size_t)arow[p] * EMB + acol[p]);
    #pragma unroll
    for (int p = 0; p < 2; p++) fb[p] = *(const float4*)(Wg + (size_t)brow[p] * EMB + bcol[p]);

    for (int it = 0; it < 32; ++it) {
        __syncthreads();
        #pragma unroll
        for (int p = 0; p < 4; p++)
            split_store4(Ah + arow[p] * A_PITCH + acol[p], A_LO, fa[p]);
        #pragma unroll
        for (int p = 0; p < 2; p++)
            split_store4(Bh + brow[p] * B_PITCH + bcol[p], B_LO, fb[p]);
        __syncthreads();

        if (it < 31) {
            const int kn = (it + 1) * 32;
            #pragma unroll
            for (int p = 0; p < 4; p++)
                fa[p] = *(const float4*)(Ag + (size_t)arow[p] * EMB + kn + acol[p]);
            #pragma unroll
            for (int p = 0; p < 2; p++)
                fb[p] = *(const float4*)(Wg + (size_t)(kn + brow[p]) * EMB + bcol[p]);
        }
        mma_step(Ah, Bh, wm, wn, lane, 0,  acc);
        mma_step(Ah, Bh, wm, wn, lane, 16, acc);
    }

    __syncthreads();
    {
        const int r0 = wm + (lane >> 2);
        const int c0 = wn + 2 * (lane & 3);
        #pragma unroll
        for (int mt = 0; mt < 2; mt++)
            #pragma unroll
            for (int nt = 0; nt < 4; nt++) {
                int r = r0 + mt * 16, c = c0 + nt * 8;
                Cs[r * 65 + c]           = acc[mt][nt][0];
                Cs[r * 65 + c + 1]       = acc[mt][nt][1];
                Cs[(r + 8) * 65 + c]     = acc[mt][nt][2];
                Cs[(r + 8) * 65 + c + 1] = acc[mt][nt][3];
            }
    }
    __syncthreads();

    float* Og = out + (size_t)(mb * 128) * EMB + nb * 64;
    const float* bg = bo + nb * 64;
    for (int i = tid; i < 8192; i += 256) {
        int r = i >> 6, c = i & 63;
        Og[(size_t)r * EMB + c] = Cs[r * 65 + c] + bg[c];
    }
}

// =========================================================================
extern "C" void kernel_launch(void* const* d_in, const int* in_sizes, int n_in,
                              void* d_out, int out_size)
{
    const float* q  = (const float*)d_in[0];
    const float* k  = (const float*)d_in[1];
    const float* v  = (const float*)d_in[2];
    const float* Wq = (const float*)d_in[3];
    const float* Wk = (const float*)d_in[4];
    const float* Wv = (const float*)d_in[5];
    const float* bq = (const float*)d_in[6];
    const float* bk = (const float*)d_in[7];
    const float* bv = (const float*)d_in[8];
    const float* Wo = (const float*)d_in[9];
    const float* bo = (const float*)d_in[10];
    float* out = (float*)d_out;

    (void)in_sizes; (void)n_in; (void)out_size;

    // 1) QKV projections via mma.sync (Q,K transposed [B,H,Dh,S]; V normal)
    proj_qkv_kernel<<<dim3(32, 16, 3), 256>>>(q, k, v, Wq, Wk, Wv, bq, bk, bv);
    // 2) flash attention (fp32, R3) -> g_ctx
    flash_kernel<<<dim3(32, 16, 2), 256, 49152>>>();
    // 3) output projection via mma.sync + bias -> d_out
    outproj_kernel<<<dim3(32, 16), 256>>>(Wo, bo, out);
}